// round 1
// baseline (speedup 1.0000x reference)
#include <cuda_runtime.h>
#include <math.h>

#define NMAX 100000
#define EMAX 3200000
#define GMAX 128
#define H 32

// Scratch (device globals: no allocation allowed in kernel_launch)
__device__ int   g_deg[NMAX];
__device__ float g_dinv[NMAX];
__device__ int   g_rowstart[NMAX + 1];
__device__ int   g_cursor[NMAX];
__device__ int   g_csr[EMAX];
__device__ float g_hs[NMAX * H];   // transformed, dinv-prescaled features
__device__ float g_x[NMAX * H];    // post-aggregation activations
__device__ float g_gsum[GMAX * H];
__device__ float g_gcnt[GMAX];

__global__ void k_init(int n, int g) {
    int i = blockIdx.x * blockDim.x + threadIdx.x;
    if (i < n) g_deg[i] = 1;            // self-loop
    if (i < g * H) g_gsum[i] = 0.f;
    if (i < g) g_gcnt[i] = 0.f;
}

__global__ void k_count(const int* __restrict__ dst, int e) {
    int i = blockIdx.x * blockDim.x + threadIdx.x;
    if (i < e) atomicAdd(&g_deg[dst[i]], 1);
}

// Single-block exclusive scan of (deg-1) -> rowstart/cursor, plus dinv.
__global__ void k_scan(int n) {
    const int K = 4;
    __shared__ int warp_sums[32];
    __shared__ int sh_carry;
    int tid = threadIdx.x, lane = tid & 31, wid = tid >> 5;
    if (tid == 0) sh_carry = 0;
    __syncthreads();
    for (int base = 0; base < n; base += 1024 * K) {
        int v[K];
        int local = 0;
#pragma unroll
        for (int k = 0; k < K; k++) {
            int i = base + tid * K + k;
            v[k] = (i < n) ? (g_deg[i] - 1) : 0;
            local += v[k];
        }
        int incl = local;
#pragma unroll
        for (int o = 1; o < 32; o <<= 1) {
            int t = __shfl_up_sync(0xffffffffu, incl, o);
            if (lane >= o) incl += t;
        }
        if (lane == 31) warp_sums[wid] = incl;
        __syncthreads();
        int carry = sh_carry;
        __syncthreads();
        if (tid == 0) {
            int run = 0;
#pragma unroll
            for (int w = 0; w < 32; w++) { int t = warp_sums[w]; warp_sums[w] = run; run += t; }
            sh_carry = carry + run;
        }
        __syncthreads();
        int excl = carry + warp_sums[wid] + (incl - local);
#pragma unroll
        for (int k = 0; k < K; k++) {
            int i = base + tid * K + k;
            if (i < n) {
                g_rowstart[i] = excl;
                g_cursor[i] = excl;
                g_dinv[i] = rsqrtf((float)g_deg[i]);
            }
            excl += v[k];
        }
        __syncthreads();
    }
    if (tid == 0) g_rowstart[n] = sh_carry;
}

__global__ void k_scatter(const int* __restrict__ src, const int* __restrict__ dst, int e) {
    int i = blockIdx.x * blockDim.x + threadIdx.x;
    if (i < e) {
        int d = dst[i];
        int p = atomicAdd(&g_cursor[d], 1);
        g_csr[p] = src[i];
    }
}

// Layer-1 transform: x is [N,1], hs[i][j] = dinv[i] * x[i] * W1[j]
__global__ void k_t1(const float* __restrict__ x, const float* __restrict__ W1, int n) {
    int idx = blockIdx.x * blockDim.x + threadIdx.x;
    if (idx < n * H) {
        int i = idx >> 5, j = idx & 31;
        g_hs[idx] = g_dinv[i] * x[i] * __ldg(&W1[j]);
    }
}

// General transform: hs = (g_x @ W) * dinv
__global__ void k_transform(const float* __restrict__ W, int n) {
    __shared__ float Ws[H * H];
    __shared__ float Xs[8 * H];
    int tid = threadIdx.x;
    for (int t = tid; t < H * H; t += 256) Ws[t] = W[t];
    int base = blockIdx.x * 8;
    int gidx = base * H + tid;
    Xs[tid] = (gidx < n * H) ? g_x[gidx] : 0.f;
    __syncthreads();
    int node = tid >> 5, j = tid & 31;
    int i = base + node;
    if (i < n) {
        float acc = 0.f;
#pragma unroll
        for (int k = 0; k < H; k++) acc += Xs[node * H + k] * Ws[k * H + j];
        g_hs[i * H + j] = acc * g_dinv[i];
    }
}

// Gather: warp per node, lane = feature. x_out = relu(dinv[i]*(self + sum_nb hs[src]) + b)
__global__ void k_gather(const float* __restrict__ b, int n) {
    int wid = (blockIdx.x * blockDim.x + threadIdx.x) >> 5;
    int lane = threadIdx.x & 31;
    if (wid >= n) return;
    int i = wid;
    float s = g_hs[i * H + lane];   // self-loop term (already dinv-scaled)
    int st = g_rowstart[i], en = g_rowstart[i + 1];
    for (int bse = st; bse < en; bse += 32) {
        int m = min(32, en - bse);
        int sidx = (lane < m) ? g_csr[bse + lane] : 0;
        for (int t = 0; t < m; t++) {
            int sj = __shfl_sync(0xffffffffu, sidx, t);
            s += g_hs[sj * H + lane];
        }
    }
    g_x[i * H + lane] = fmaxf(s * g_dinv[i] + __ldg(&b[lane]), 0.f);
}

// Per-node theta head + per-graph pooling accumulation. Warp per node.
__global__ void k_head(const int* __restrict__ batch,
                       const float* __restrict__ Wt1, const float* __restrict__ bt1,
                       const float* __restrict__ Wt2, const float* __restrict__ bt2,
                       float* __restrict__ out, int n) {
    int wid = (blockIdx.x * blockDim.x + threadIdx.x) >> 5;
    int lane = threadIdx.x & 31;
    if (wid >= n) return;
    int i = wid;
    float xr = g_x[i * H + lane];
    float acc = __ldg(&bt1[lane]);
#pragma unroll
    for (int k = 0; k < H; k++)
        acc += __shfl_sync(0xffffffffu, xr, k) * __ldg(&Wt1[k * H + lane]);
    float p = fmaxf(acc, 0.f) * __ldg(&Wt2[lane]);
#pragma unroll
    for (int o = 16; o > 0; o >>= 1) p += __shfl_xor_sync(0xffffffffu, p, o);
    int g = batch[i];
    atomicAdd(&g_gsum[g * H + lane], xr);
    if (lane == 0) {
        atomicAdd(&g_gcnt[g], 1.f);
        float sgm = p + __ldg(&bt2[0]);
        out[i] = 3.14159265358979323846f / (1.f + expf(-sgm));
    }
}

// Per-graph MLP head. Warp per graph.
__global__ void k_graph(const float* __restrict__ Wg1, const float* __restrict__ bg1,
                        const float* __restrict__ Wg2, const float* __restrict__ bg2,
                        float* __restrict__ out, int n, int g) {
    int wid = (blockIdx.x * blockDim.x + threadIdx.x) >> 5;
    int lane = threadIdx.x & 31;
    if (wid >= g) return;
    float cnt = fmaxf(g_gcnt[wid], 1.f);
    float ge = g_gsum[wid * H + lane] / cnt;
    float acc = __ldg(&bg1[lane]);
#pragma unroll
    for (int k = 0; k < H; k++)
        acc += __shfl_sync(0xffffffffu, ge, k) * __ldg(&Wg1[k * H + lane]);
    float t = fmaxf(acc, 0.f);
    float p0 = t * __ldg(&Wg2[lane * 2 + 0]);
    float p1 = t * __ldg(&Wg2[lane * 2 + 1]);
#pragma unroll
    for (int o = 16; o > 0; o >>= 1) {
        p0 += __shfl_xor_sync(0xffffffffu, p0, o);
        p1 += __shfl_xor_sync(0xffffffffu, p1, o);
    }
    if (lane == 0) {
        const float TWO_PI = 6.28318530717958647692f;
        out[n + wid * 2 + 0] = TWO_PI / (1.f + expf(-(p0 + __ldg(&bg2[0]))));
        out[n + wid * 2 + 1] = TWO_PI / (1.f + expf(-(p1 + __ldg(&bg2[1]))));
    }
}

extern "C" void kernel_launch(void* const* d_in, const int* in_sizes, int n_in,
                              void* d_out, int out_size) {
    const float* x   = (const float*)d_in[0];
    const int*   ei  = (const int*)d_in[1];
    const int*   bat = (const int*)d_in[2];
    const float* W1  = (const float*)d_in[3];
    const float* b1  = (const float*)d_in[4];
    const float* W2  = (const float*)d_in[5];
    const float* b2  = (const float*)d_in[6];
    const float* W3  = (const float*)d_in[7];
    const float* b3  = (const float*)d_in[8];
    const float* Wt1 = (const float*)d_in[9];
    const float* bt1 = (const float*)d_in[10];
    const float* Wt2 = (const float*)d_in[11];
    const float* bt2 = (const float*)d_in[12];
    const float* Wg1 = (const float*)d_in[13];
    const float* bg1 = (const float*)d_in[14];
    const float* Wg2 = (const float*)d_in[15];
    const float* bg2 = (const float*)d_in[16];
    float* out = (float*)d_out;

    int N = in_sizes[0];            // x is [N,1]
    int E = in_sizes[1] / 2;        // edge_index is [2,E]
    int G = (out_size - N) / 2;     // out = theta[N] ++ beta_gamma[G,2]

    const int* src = ei;
    const int* dst = ei + E;

    const int TB = 256;
    int nb_n  = (N + TB - 1) / TB;
    int nb_e  = (E + TB - 1) / TB;
    int nb_w  = (N * 32 + TB - 1) / TB;     // warp-per-node kernels
    int nb_t  = (N + 7) / 8;                // 8 nodes per block transforms
    int nb_g  = (G * 32 + TB - 1) / TB;

    // CSR build
    k_init<<<nb_n, TB>>>(N, G);
    k_count<<<nb_e, TB>>>(dst, E);
    k_scan<<<1, 1024>>>(N);
    k_scatter<<<nb_e, TB>>>(src, dst, E);

    // Layer 1
    k_t1<<<(N * H + TB - 1) / TB, TB>>>(x, W1, N);
    k_gather<<<nb_w, TB>>>(b1, N);
    // Layer 2
    k_transform<<<nb_t, TB>>>(W2, N);
    k_gather<<<nb_w, TB>>>(b2, N);
    // Layer 3
    k_transform<<<nb_t, TB>>>(W3, N);
    k_gather<<<nb_w, TB>>>(b3, N);

    // Heads
    k_head<<<nb_w, TB>>>(bat, Wt1, bt1, Wt2, bt2, out, N);
    k_graph<<<nb_g, TB>>>(Wg1, bg1, Wg2, bg2, out, N, G);
}